// round 2
// baseline (speedup 1.0000x reference)
#include <cuda_runtime.h>

// Problem constants (fixed instance: B=32, T=512, C=6625, L=32)
#define BB 32
#define TT 512
#define CC 6625
#define LL 32
#define SS 65        // 2L+1 extended states
#define SP 66        // padded row stride (even -> float2-aligned rows)
#define BLANK_ID 6624
#define LOG2E 1.4426950408889634f
#define LN2f   0.6931471805599453f
#define NEG2  (-1e30f)

// Static device scratch (no runtime allocation)
__device__ float g_emit[(size_t)BB * TT * SP];   // log2-domain normalized emissions [b][t][s]
__device__ float g_partial[BB];                  // per-batch loss / target_length

__device__ __forceinline__ float ex2f_(float x) {
    float y; asm("ex2.approx.ftz.f32 %0, %1;" : "=f"(y) : "f"(x)); return y;
}
__device__ __forceinline__ float lg2f_(float x) {
    float y; asm("lg2.approx.ftz.f32 %0, %1;" : "=f"(y) : "f"(x)); return y;
}

// ---------------------------------------------------------------------------
// Kernel 1: per-(batch, state) column gather + time-axis logsumexp.
// Grid (SS, BB), 128 threads. Each block handles one extended-label class
// column: reads log_probs[b, :, c] (strided), computes lse over T, writes
// emit2[b][t][s] = (x - lse) * log2(e) into scratch.
// ---------------------------------------------------------------------------
__global__ void gather_lse_kernel(const float* __restrict__ lp,
                                  const int* __restrict__ targets) {
    const int s   = blockIdx.x;   // 0..SS-1
    const int b   = blockIdx.y;   // 0..BB-1
    const int tid = threadIdx.x;  // 0..127

    const int c = (s & 1) ? targets[b * LL + ((s - 1) >> 1)] : BLANK_ID;
    const float* col = lp + (size_t)b * TT * CC + c;

    float v[4];
#pragma unroll
    for (int k = 0; k < 4; ++k)
        v[k] = __ldg(col + (size_t)(tid + k * 128) * CC);

    // block max
    float m = fmaxf(fmaxf(v[0], v[1]), fmaxf(v[2], v[3]));
#pragma unroll
    for (int o = 16; o; o >>= 1) m = fmaxf(m, __shfl_xor_sync(0xffffffffu, m, o));
    __shared__ float redm[4];
    const int w = tid >> 5;
    if ((tid & 31) == 0) redm[w] = m;
    __syncthreads();
    m = fmaxf(fmaxf(redm[0], redm[1]), fmaxf(redm[2], redm[3]));

    // block sum of 2^((v-m)*log2e)
    float sum = 0.f;
#pragma unroll
    for (int k = 0; k < 4; ++k) sum += ex2f_((v[k] - m) * LOG2E);
#pragma unroll
    for (int o = 16; o; o >>= 1) sum += __shfl_xor_sync(0xffffffffu, sum, o);
    __shared__ float reds[4];
    if ((tid & 31) == 0) reds[w] = sum;
    __syncthreads();
    sum = reds[0] + reds[1] + reds[2] + reds[3];

    const float lse2 = m * LOG2E + lg2f_(sum);   // log2-domain logsumexp

    float* dst = g_emit + (size_t)b * TT * SP + s;
#pragma unroll
    for (int k = 0; k < 4; ++k)
        dst[(size_t)(tid + k * 128) * SP] = v[k] * LOG2E - lse2;
}

// ---------------------------------------------------------------------------
// Kernel 2: CTC alpha recursion. One warp per batch. Lane i owns states
// 2i (blank) and 2i+1 (label i); lane 31 also owns state 64 (final blank).
// log2-domain logaddexp via ex2/lg2 approx. Emissions prefetched 4 ahead.
//
// Transition structure (one shfl per step):
//   even state 2i   <- {2i (self aE), 2i-1 (prev lane aO)}
//   odd  state 2i+1 <- {2i+1 (self aO), 2i (self aE), 2i-1 (prev lane aO, if allow)}
//   state 64        <- {64 (aX), 63 (lane31 aO)}
// ---------------------------------------------------------------------------
__global__ void ctc_kernel(const int* __restrict__ targets,
                           const int* __restrict__ ilens,
                           const int* __restrict__ tlens) {
    const int b    = blockIdx.x;
    const int lane = threadIdx.x;  // 0..31
    const float* em = g_emit + (size_t)b * TT * SP;

    const int tgt  = targets[b * LL + lane];
    const int prev = (lane > 0) ? targets[b * LL + lane - 1] : BLANK_ID;
    const bool allow = (tgt != BLANK_ID) && (tgt != prev);  // skip-transition for odd state

    float aE = NEG2, aO = NEG2, aX = NEG2;
    if (lane == 0) { aE = em[0]; aO = em[1]; }   // alpha0[0], alpha0[1]

    // prefetch emissions for t = 1..4
    float eE[4], eO[4], eX[4];
#pragma unroll
    for (int k = 0; k < 4; ++k) {
        const int t = 1 + k;
        const float2* p = (const float2*)(em + (size_t)t * SP);
        float2 vv = p[lane];
        eE[k] = vv.x; eO[k] = vv.y;
        eX[k] = em[(size_t)t * SP + 64];
    }

    const int ilen = ilens[b];

#pragma unroll 4
    for (int t = 1; t < TT; ++t) {
        const int slot = (t - 1) & 3;

        float pO = __shfl_up_sync(0xffffffffu, aO, 1);  // prev lane's odd state (2i-1)
        if (lane == 0) pO = NEG2;

        // even state 2i: logaddexp(aE, pO) + emit
        const float m1 = fmaxf(aE, pO);
        const float d1 = fminf(aE, pO) - m1;
        const float nE = m1 + lg2f_(1.0f + ex2f_(d1)) + eE[slot];

        // odd state 2i+1: logaddexp3(aO, aE, allow ? pO : -inf) + emit
        const float sk = allow ? pO : NEG2;
        const float m2 = fmaxf(fmaxf(aO, aE), sk);
        const float s2 = ex2f_(aO - m2) + ex2f_(aE - m2) + ex2f_(sk - m2);
        const float nO = m2 + lg2f_(s2) + eO[slot];

        // state 64 (lane 31): logaddexp(aX, aO_old[63]) + emit
        const float m3 = fmaxf(aX, aO);
        const float d3 = fminf(aX, aO) - m3;
        const float nX = m3 + lg2f_(1.0f + ex2f_(d3)) + eX[slot];

        if (t < ilen) { aE = nE; aO = nO; aX = nX; }

        // prefetch t+4 into the slot just consumed
        const int tp = t + 4;
        if (tp < TT) {
            const float2* p = (const float2*)(em + (size_t)tp * SP);
            float2 vv = p[lane];
            eE[slot] = vv.x; eO[slot] = vv.y;
            eX[slot] = em[(size_t)tp * SP + 64];
        }
    }

    __shared__ float fin[SS];
    fin[2 * lane]     = aE;
    fin[2 * lane + 1] = aO;
    if (lane == 31) fin[64] = aX;
    __syncwarp();

    if (lane == 0) {
        const int tl = tlens[b];
        const int i1 = 2 * tl;
        const int i2 = (2 * tl - 1 > 0) ? (2 * tl - 1) : 0;
        const float l1 = fin[i1];
        const float l2 = fin[i2];
        const float mm = fmaxf(l1, l2);
        const float dd = fminf(l1, l2) - mm;
        const float ll2 = mm + lg2f_(1.0f + ex2f_(dd));   // log2-domain logaddexp
        float loss = -ll2 * LN2f;                          // back to natural log
        if (loss > 1e20f) loss = 0.0f;                     // zero_infinity
        const int dn = (tl > 1) ? tl : 1;
        g_partial[b] = loss / (float)dn;
    }
}

// ---------------------------------------------------------------------------
// Kernel 3: deterministic mean over batches.
// ---------------------------------------------------------------------------
__global__ void finalize_kernel(float* __restrict__ out) {
    float v = g_partial[threadIdx.x];
#pragma unroll
    for (int o = 16; o; o >>= 1) v += __shfl_xor_sync(0xffffffffu, v, o);
    if (threadIdx.x == 0) out[0] = v * (1.0f / (float)BB);
}

extern "C" void kernel_launch(void* const* d_in, const int* in_sizes, int n_in,
                              void* d_out, int out_size) {
    const float* lp      = (const float*)d_in[0];
    const int*   targets = (const int*)d_in[1];
    const int*   ilens   = (const int*)d_in[2];
    const int*   tlens   = (const int*)d_in[3];
    (void)in_sizes; (void)n_in; (void)out_size;

    gather_lse_kernel<<<dim3(SS, BB), 128>>>(lp, targets);
    ctc_kernel<<<BB, 32>>>(targets, ilens, tlens);
    finalize_kernel<<<1, BB>>>((float*)d_out);
}

// round 3
// speedup vs baseline: 1.2928x; 1.2928x over previous
#include <cuda_runtime.h>

// Problem constants (fixed instance: B=32, T=512, C=6625, L=32)
#define BB 32
#define TT 512
#define CC 6625
#define LL 32
#define SS 65        // 2L+1 extended states
#define NST 33       // stored emissions per (b,t): 32 labels + 1 blank
#define RSP 34       // row stride: [0..31]=labels, [32]=blank_lin, [33]=row max (log2)
#define BLANK_ID 6624
#define LOG2E 1.4426950408889634f
#define LN2d  0.6931471805599453
#define NEG2  (-1e30f)

// Static device scratch (no runtime allocation)
__device__ float g_emit[(size_t)BB * TT * RSP];
__device__ float g_partial[BB];

__device__ __forceinline__ float ex2f_(float x) {
    float y; asm("ex2.approx.ftz.f32 %0, %1;" : "=f"(y) : "f"(x)); return y;
}
__device__ __forceinline__ float lg2f_(float x) {
    float y; asm("lg2.approx.ftz.f32 %0, %1;" : "=f"(y) : "f"(x)); return y;
}

// ---------------------------------------------------------------------------
// Kernel 1: per-(batch, class) column gather + time-axis logsumexp.
// Grid (33, BB): s<32 -> label s, s==32 -> blank (deduplicated: stored once).
// Writes log2-domain normalized emissions into g_emit[b][t][s].
// ---------------------------------------------------------------------------
__global__ void gather_lse_kernel(const float* __restrict__ lp,
                                  const int* __restrict__ targets) {
    const int s   = blockIdx.x;   // 0..32
    const int b   = blockIdx.y;
    const int tid = threadIdx.x;  // 0..127

    const int c = (s < 32) ? targets[b * LL + s] : BLANK_ID;
    const float* col = lp + (size_t)b * TT * CC + c;

    float v[4];
#pragma unroll
    for (int k = 0; k < 4; ++k)
        v[k] = __ldg(col + (size_t)(tid + k * 128) * CC);

    // block max
    float m = fmaxf(fmaxf(v[0], v[1]), fmaxf(v[2], v[3]));
#pragma unroll
    for (int o = 16; o; o >>= 1) m = fmaxf(m, __shfl_xor_sync(0xffffffffu, m, o));
    __shared__ float redm[4];
    const int w = tid >> 5;
    if ((tid & 31) == 0) redm[w] = m;
    __syncthreads();
    m = fmaxf(fmaxf(redm[0], redm[1]), fmaxf(redm[2], redm[3]));

    // block sum of 2^((v-m)*log2e)
    float sum = 0.f;
#pragma unroll
    for (int k = 0; k < 4; ++k) sum += ex2f_((v[k] - m) * LOG2E);
#pragma unroll
    for (int o = 16; o; o >>= 1) sum += __shfl_xor_sync(0xffffffffu, sum, o);
    __shared__ float reds[4];
    if ((tid & 31) == 0) reds[w] = sum;
    __syncthreads();
    sum = reds[0] + reds[1] + reds[2] + reds[3];

    const float lse2 = m * LOG2E + lg2f_(sum);   // log2-domain logsumexp over t

    float* dst = g_emit + (size_t)b * TT * RSP + s;
#pragma unroll
    for (int k = 0; k < 4; ++k)
        dst[(size_t)(tid + k * 128) * RSP] = v[k] * LOG2E - lse2;
}

// ---------------------------------------------------------------------------
// Kernel 1b: per-(b,t) row normalization to linear domain.
// One warp per row: mx = max over the 33 log2 emissions; rewrite row with
// lin = 2^(v - mx); stash blank_lin at [32] and mx at [33].
// ---------------------------------------------------------------------------
__global__ void row_norm_kernel() {
    const int lane = threadIdx.x & 31;
    const int w    = threadIdx.x >> 5;
    const int t    = blockIdx.x * 4 + w;
    const int b    = blockIdx.y;

    float* row = g_emit + ((size_t)b * TT + t) * RSP;
    const float lv = row[lane];   // label s = lane
    const float bv = row[32];     // blank (broadcast load)

    float mx = lv;
#pragma unroll
    for (int o = 16; o; o >>= 1) mx = fmaxf(mx, __shfl_xor_sync(0xffffffffu, mx, o));
    mx = fmaxf(mx, bv);

    row[lane] = ex2f_(lv - mx);
    if (lane == 0) {
        row[32] = ex2f_(bv - mx);
        row[33] = mx;             // log2-domain factored constant
    }
}

// ---------------------------------------------------------------------------
// Kernel 2: CTC alpha recursion in LINEAR domain. One warp per batch.
// Lane i owns states 2i (blank, aE) and 2i+1 (label i, aO); lane 31 also
// owns state 64 (aX). Dead states are exactly 0. Per step:
//   nE = (aE + pO) * blank_lin
//   nO = (aO + aE + (allow ? pO : 0)) * label_lin
//   nX = (aX + aO) * blank_lin        (lane 31)
// Warp-uniform power-of-2 rescale every 16 steps; exponent tracked exactly.
// ---------------------------------------------------------------------------
__global__ void ctc_kernel(const int* __restrict__ targets,
                           const int* __restrict__ ilens,
                           const int* __restrict__ tlens) {
    const int b    = blockIdx.x;
    const int lane = threadIdx.x;
    const float* em = g_emit + (size_t)b * TT * RSP;

    const int tgt  = targets[b * LL + lane];
    const int prev = (lane > 0) ? targets[b * LL + lane - 1] : BLANK_ID;
    const bool allow = (tgt != BLANK_ID) && (tgt != prev);
    const int ilen = ilens[b];

    // t = 0 init
    const float l0  = em[lane];
    const float2 bm0 = *(const float2*)(em + 32);
    float aE = (lane == 0) ? bm0.x : 0.f;
    float aO = (lane == 0) ? l0    : 0.f;
    float aX = 0.f;
    double smx = (double)bm0.y;   // sum of factored per-t constants (log2 units)
    int e_acc = 0;                // accumulated renorm exponents (log2 units)

    // prefetch t = 1..8
    float eL[8], eB[8], eM[8];
#pragma unroll
    for (int k = 0; k < 8; ++k) {
        const int t = 1 + k;
        eL[k] = em[(size_t)t * RSP + lane];
        const float2 bm = *(const float2*)(em + (size_t)t * RSP + 32);
        eB[k] = bm.x; eM[k] = bm.y;
    }

#pragma unroll 8
    for (int t = 1; t < TT; ++t) {
        const int slot = (t - 1) & 7;

        float pO = __shfl_up_sync(0xffffffffu, aO, 1);
        if (lane == 0) pO = 0.f;

        const float s1 = aO + aE;            // independent of shfl -> overlaps
        const float sk = allow ? pO : 0.f;
        const float nO = (s1 + sk) * eL[slot];
        const float nE = (aE + pO) * eB[slot];
        const float nX = (aX + aO) * eB[slot];

        if (t < ilen) {
            aE = nE; aO = nO; aX = nX;
            smx += (double)eM[slot];
        }

        if ((t & 15) == 0) {   // periodic exact power-of-2 renorm
            float m = fmaxf(fmaxf(aE, aO), aX);
#pragma unroll
            for (int o = 16; o; o >>= 1) m = fmaxf(m, __shfl_xor_sync(0xffffffffu, m, o));
            if (m > 0.f) {
                const int e = ((__float_as_int(m) >> 23) & 255) - 127;
                const float sc = __int_as_float((127 - e) << 23);
                aE *= sc; aO *= sc; aX *= sc;
                e_acc += e;
            }
        }

        const int tp = t + 8;
        if (tp < TT) {
            eL[slot] = em[(size_t)tp * RSP + lane];
            const float2 bm = *(const float2*)(em + (size_t)tp * RSP + 32);
            eB[slot] = bm.x; eM[slot] = bm.y;
        }
    }

    __shared__ float fin[SS];
    fin[2 * lane]     = aE;
    fin[2 * lane + 1] = aO;
    if (lane == 31) fin[64] = aX;
    __syncwarp();

    if (lane == 0) {
        const int tl = tlens[b];
        const int i1 = 2 * tl;
        const int i2 = (2 * tl - 1 > 0) ? (2 * tl - 1) : 0;
        const float tot = fin[i1] + fin[i2];
        float loss;
        if (tot > 0.f) {
            const double ll2 = (double)lg2f_(tot) + (double)e_acc + smx;
            loss = (float)(-LN2d * ll2);
            if (!(loss < 1e20f)) loss = 0.f;   // zero_infinity
        } else {
            loss = 0.f;                        // total prob 0 -> inf loss -> 0
        }
        const int dn = (tl > 1) ? tl : 1;
        g_partial[b] = loss / (float)dn;
    }
}

// ---------------------------------------------------------------------------
// Kernel 3: deterministic mean over batches.
// ---------------------------------------------------------------------------
__global__ void finalize_kernel(float* __restrict__ out) {
    float v = g_partial[threadIdx.x];
#pragma unroll
    for (int o = 16; o; o >>= 1) v += __shfl_xor_sync(0xffffffffu, v, o);
    if (threadIdx.x == 0) out[0] = v * (1.0f / (float)BB);
}

extern "C" void kernel_launch(void* const* d_in, const int* in_sizes, int n_in,
                              void* d_out, int out_size) {
    const float* lp      = (const float*)d_in[0];
    const int*   targets = (const int*)d_in[1];
    const int*   ilens   = (const int*)d_in[2];
    const int*   tlens   = (const int*)d_in[3];
    (void)in_sizes; (void)n_in; (void)out_size;

    gather_lse_kernel<<<dim3(NST, BB), 128>>>(lp, targets);
    row_norm_kernel<<<dim3(TT / 4, BB), 128>>>();
    ctc_kernel<<<BB, 32>>>(targets, ilens, tlens);
    finalize_kernel<<<1, BB>>>((float*)d_out);
}

// round 4
// speedup vs baseline: 1.9091x; 1.4768x over previous
#include <cuda_runtime.h>

// Problem constants (fixed instance: B=32, T=512, C=6625, L=32)
#define BB 32
#define TT 512
#define CC 6625
#define LL 32
#define SS 65        // 2L+1 extended states
#define RSP 33       // row stride: [0..31]=label lin emissions, [32]=blank lin
#define BLANK_ID 6624
#define LOG2E 1.4426950408889634f
#define LN2d  0.6931471805599453
#define CSHIFT 10.0f     // constant log2 boost per emission (exactly representable)
#define RN_TARGET 50     // renorm target exponent: keep warp max near 2^50

// Static device scratch (no runtime allocation)
__device__ float g_emit[(size_t)BB * TT * RSP];   // linear-domain boosted emissions
__device__ float g_partial[BB];
__device__ int   g_done = 0;                      // cross-block completion counter

__device__ __forceinline__ float ex2f_(float x) {
    float y; asm("ex2.approx.ftz.f32 %0, %1;" : "=f"(y) : "f"(x)); return y;
}
__device__ __forceinline__ float lg2f_(float x) {
    float y; asm("lg2.approx.ftz.f32 %0, %1;" : "=f"(y) : "f"(x)); return y;
}

// ---------------------------------------------------------------------------
// Kernel 1: per-(batch, class) column gather + time-axis logsumexp + direct
// linearization. Grid (33, BB): s<32 -> label s, s==32 -> blank.
// Writes emit_lin = 2^(lv + CSHIFT), lv = log2-normalized emission.
// ---------------------------------------------------------------------------
__global__ void gather_lse_kernel(const float* __restrict__ lp,
                                  const int* __restrict__ targets) {
    const int s   = blockIdx.x;   // 0..32
    const int b   = blockIdx.y;
    const int tid = threadIdx.x;  // 0..127

    const int c = (s < 32) ? targets[b * LL + s] : BLANK_ID;
    const float* col = lp + (size_t)b * TT * CC + c;

    float v[4];
#pragma unroll
    for (int k = 0; k < 4; ++k)
        v[k] = __ldcs(col + (size_t)(tid + k * 128) * CC);

    // block max
    float m = fmaxf(fmaxf(v[0], v[1]), fmaxf(v[2], v[3]));
#pragma unroll
    for (int o = 16; o; o >>= 1) m = fmaxf(m, __shfl_xor_sync(0xffffffffu, m, o));
    __shared__ float redm[4];
    const int w = tid >> 5;
    if ((tid & 31) == 0) redm[w] = m;
    __syncthreads();
    m = fmaxf(fmaxf(redm[0], redm[1]), fmaxf(redm[2], redm[3]));

    // block sum of 2^((v-m)*log2e)
    float sum = 0.f;
#pragma unroll
    for (int k = 0; k < 4; ++k) sum += ex2f_((v[k] - m) * LOG2E);
#pragma unroll
    for (int o = 16; o; o >>= 1) sum += __shfl_xor_sync(0xffffffffu, sum, o);
    __shared__ float reds[4];
    if ((tid & 31) == 0) reds[w] = sum;
    __syncthreads();
    sum = reds[0] + reds[1] + reds[2] + reds[3];

    const float lse2 = m * LOG2E + lg2f_(sum);   // log2-domain logsumexp over t

    float* dst = g_emit + (size_t)b * TT * RSP + s;
#pragma unroll
    for (int k = 0; k < 4; ++k)
        dst[(size_t)(tid + k * 128) * RSP] =
            ex2f_(v[k] * LOG2E - lse2 + CSHIFT);
}

// ---------------------------------------------------------------------------
// Kernel 2: CTC alpha recursion in LINEAR domain + in-kernel batch mean.
// One warp per batch (32 blocks x 32 threads). Lane i owns states 2i (aE)
// and 2i+1 (aO); lane 31 also owns state 64 (aX). Per step (chain ~38cyc):
//   nE = (aE + pO*zb) * eB       (zb: lane0 mask)
//   nO = (aO + aE + pO*za) * eL  (za: skip-allowed mask)
//   nX = (aX + aO) * eB
// Exact power-of-2 renorm every 16 steps targets 2^RN_TARGET so the answer
// states (63/64) stay in fp32 NORMAL range (no denormal squash).
// ---------------------------------------------------------------------------
__global__ void ctc_kernel(const int* __restrict__ targets,
                           const int* __restrict__ ilens,
                           const int* __restrict__ tlens,
                           float* __restrict__ out) {
    const int b    = blockIdx.x;
    const int lane = threadIdx.x;
    const float* em = g_emit + (size_t)b * TT * RSP;

    const int tgt  = targets[b * LL + lane];
    const int prev = (lane > 0) ? targets[b * LL + lane - 1] : BLANK_ID;
    const float za = (lane > 0 && tgt != BLANK_ID && tgt != prev) ? 1.f : 0.f;
    const float zb = (lane > 0) ? 1.f : 0.f;
    int ilen = ilens[b];
    if (ilen > TT) ilen = TT;

    // t = 0 init
    float aE = (lane == 0) ? em[32] : 0.f;    // state 0: blank emission
    float aO = (lane == 0) ? em[0]  : 0.f;    // state 1: label 0 emission
    float aX = 0.f;
    int   SH = 0;                             // accumulated renorm log2 shifts

    // prefetch t = 1..8
    float eL[8], eB[8];
#pragma unroll
    for (int k = 0; k < 8; ++k) {
        const int t = 1 + k;
        eL[k] = em[(size_t)t * RSP + lane];
        eB[k] = em[(size_t)t * RSP + 32];
    }

#pragma unroll 8
    for (int t = 1; t < TT; ++t) {
        const int slot = (t - 1) & 7;

        float pO = __shfl_up_sync(0xffffffffu, aO, 1);
        const float s1 = aO + aE;             // independent of shfl -> overlaps

        const float nO = fmaf(pO, za, s1) * eL[slot];
        const float nE = fmaf(pO, zb, aE) * eB[slot];
        const float nX = (aX + aO) * eB[slot];

        if (t < ilen) { aE = nE; aO = nO; aX = nX; }

        if ((t & 15) == 0) {   // periodic exact power-of-2 renorm to 2^RN_TARGET
            float m = fmaxf(fmaxf(aE, aO), aX);
#pragma unroll
            for (int o = 16; o; o >>= 1) m = fmaxf(m, __shfl_xor_sync(0xffffffffu, m, o));
            if (m > 0.f) {
                const int e = ((__float_as_int(m) >> 23) & 255) - 127;
                int sh = RN_TARGET - e;
                if (sh > 127)  sh = 127;
                if (sh < -126) sh = -126;
                const float sc = __int_as_float((127 + sh) << 23);  // exact 2^sh
                aE *= sc; aO *= sc; aX *= sc;
                SH += sh;
            }
        }

        const int tp = t + 8;
        if (tp < TT) {
            eL[slot] = em[(size_t)tp * RSP + lane];
            eB[slot] = em[(size_t)tp * RSP + 32];
        }
    }

    __shared__ float fin[SS];
    fin[2 * lane]     = aE;
    fin[2 * lane + 1] = aO;
    if (lane == 31) fin[64] = aX;
    __syncwarp();

    if (lane == 0) {
        const int tl = tlens[b];
        const int i1 = 2 * tl;
        const int i2 = (2 * tl - 1 > 0) ? (2 * tl - 1) : 0;
        const float tot = fin[i1] + fin[i2];
        float loss;
        if (tot > 0.f) {
            // stored = true * 2^(CSHIFT*ilen + SH)
            const double ll2 = (double)lg2f_(tot)
                             - (double)SH - (double)CSHIFT * (double)ilen;
            loss = (float)(-LN2d * ll2);
            if (!(loss < 1e20f)) loss = 0.f;   // zero_infinity
        } else {
            loss = 0.f;                        // zero total prob -> inf -> 0
        }
        const int dn = (tl > 1) ? tl : 1;
        g_partial[b] = loss / (float)dn;
        __threadfence();
    }
    __syncwarp();

    // deterministic last-block batch mean (fixed-tree reduction, counter reset)
    int old = 0;
    if (lane == 0) old = atomicAdd(&g_done, 1);
    old = __shfl_sync(0xffffffffu, old, 0);
    if (old == BB - 1) {
        float v = *((volatile float*)&g_partial[lane]);
#pragma unroll
        for (int o = 16; o; o >>= 1) v += __shfl_xor_sync(0xffffffffu, v, o);
        if (lane == 0) {
            out[0] = v * (1.0f / (float)BB);
            g_done = 0;                        // reset for next graph replay
        }
    }
}

extern "C" void kernel_launch(void* const* d_in, const int* in_sizes, int n_in,
                              void* d_out, int out_size) {
    const float* lp      = (const float*)d_in[0];
    const int*   targets = (const int*)d_in[1];
    const int*   ilens   = (const int*)d_in[2];
    const int*   tlens   = (const int*)d_in[3];
    (void)in_sizes; (void)n_in; (void)out_size;

    gather_lse_kernel<<<dim3(RSP, BB), 128>>>(lp, targets);
    ctc_kernel<<<BB, 32>>>(targets, ilens, tlens, (float*)d_out);
}